// round 16
// baseline (speedup 1.0000x reference)
#include <cuda_runtime.h>
#include <cstdint>

#define TT 512      // time steps
#define NB 512      // batch
#define CC 80       // classes
#define SS 128      // max target len
#define WPB 4       // warps (batch elems) per block
#define NBC (NB*CC) // row stride in floats

// exact power of two 2^e, exponent clamped to normal range
static __device__ __forceinline__ float exp2c(int e) {
    e = max(-126, min(127, e));
    return __int_as_float((e + 127) << 23);
}

struct WState {
    float a[9];      // cells s = 8*lane + j (j=0..7); a[8] = cell 256, lane 31 only
    float sk[4];     // skip multiplier for label cells j=1,3,5,7
    float m31;       // 1.0 on lane 31, else 0 (gates cell 256)
    float pAr;       // boundary alpha a[7] from lane-1 (pre-rescale snapshot)
    int elane;       // per-lane exponent: true alpha = a * 2^elane
    int eprev;       // lane-1's elane at snapshot time
    bool empty;      // lane has no probability mass yet
};

// Core recurrence given this lane's emissions g[5] = {blank, label0..3}.
// Byte-identical math to the R13 kernel (proven rel_err 2.54e-7).
template <bool RESC>
static __device__ __forceinline__ void ctc_core(WState& S, int lane, const float (&g)[5])
{
    // exponent alignment with left neighbor (branch-free; empty lanes adopt)
    int de = S.eprev - S.elane;
    S.elane = S.empty ? S.eprev : S.elane;
    de      = S.empty ? 0 : de;
    float f  = exp2c(de);
    float pA = S.pAr * f;

    // descending update: old values read before overwrite
    S.a[8] = fmaf(S.m31, S.a[7], S.a[8]) * g[0];                              // s=256 (blank, lane31)
    { float tv = S.a[7] + S.a[6]; tv = fmaf(S.a[5], S.sk[3], tv); S.a[7] = tv * g[4]; }
    S.a[6] = (S.a[6] + S.a[5]) * g[0];                                        // blank: no skip
    { float tv = S.a[5] + S.a[4]; tv = fmaf(S.a[3], S.sk[2], tv); S.a[5] = tv * g[3]; }
    S.a[4] = (S.a[4] + S.a[3]) * g[0];
    { float tv = S.a[3] + S.a[2]; tv = fmaf(S.a[1], S.sk[1], tv); S.a[3] = tv * g[2]; }
    S.a[2] = (S.a[2] + S.a[1]) * g[0];
    { float tv = S.a[1] + S.a[0]; tv = fmaf(pA,     S.sk[0], tv); S.a[1] = tv * g[1]; }
    S.a[0] = (S.a[0] + pA) * g[0];

    if (pA > 0.f) S.empty = false;   // only entry point for new mass

    // boundary snapshot for NEXT step (pre-rescale value + current exponent)
    S.pAr   = __shfl_up_sync(0xffffffffu, S.a[7], 1);
    S.eprev = __shfl_up_sync(0xffffffffu, S.elane, 1);
    if (lane == 0) { S.pAr = 0.f; S.eprev = S.elane; }

    if (RESC) {   // branch-free per-lane power-of-2 renormalization
        float m = fmaxf(fmaxf(fmaxf(S.a[0], S.a[1]), fmaxf(S.a[2], S.a[3])),
                        fmaxf(fmaxf(S.a[4], S.a[5]),
                              fmaxf(fmaxf(S.a[6], S.a[7]), S.a[8])));
        bool nz = m > 0.f;
        int e = nz ? (((__float_as_int(m) >> 23) & 255) - 127) : 0;
        float sc = exp2c(-e);
#pragma unroll
        for (int j = 0; j < 9; j++) S.a[j] *= sc;
        S.elane += e;
        S.empty = !nz;
    }
}

static __device__ __forceinline__ void exp5(float (&dst)[5], const float (&src)[5]) {
#pragma unroll
    for (int j = 0; j < 5; j++) dst[j] = __expf(src[j]);
}

// One block step. E = slot of row t+1 (exp'd into PW); same slot is then
// refilled by LDG with row t+5 (WAR on the regs orders it after the exp read).
// PFI = compile-time row offset within the block's pointer base (row tb+5).
template <int E, int PFI, bool RESC>
static __device__ __forceinline__ void bstep(
    WState& S, int lane, float (&RAW)[4][5], const float (&PU)[5], float (&PW)[5],
    const float* pB, const float* p0, const float* p1,
    const float* p2, const float* p3, bool okpf)
{
    exp5(PW, RAW[E]);                    // p(row t+1) for next step
    if (okpf) {                          // prefetch row tb+5+PFI into slot E
        RAW[E][0] = pB[PFI * NBC];
        RAW[E][1] = p0[PFI * NBC];
        RAW[E][2] = p1[PFI * NBC];
        RAW[E][3] = p2[PFI * NBC];
        RAW[E][4] = p3[PFI * NBC];
    }
    ctc_core<RESC>(S, lane, PU);         // cells with p(row t)
}

__global__ __launch_bounds__(WPB * 32)
void ctc_kernel(const float* __restrict__ lp,   // (T, N, C)
                const int*   __restrict__ tgt,  // (N, S)
                const int*   __restrict__ ilen, // (N,)
                const int*   __restrict__ tlen, // (N,)
                float*       __restrict__ out,  // (N,)
                int nb)
{
    __shared__ float dmp[WPB][264];   // finalize dump (257 cells)
    __shared__ int   ed[WPB][32];     // per-lane exponents at finalize

    const int lane = threadIdx.x & 31;
    const int w    = threadIdx.x >> 5;
    const int n    = blockIdx.x * WPB + w;
    if (n >= nb) return;

    const int Tn = ilen[n];
    const int tl = tlen[n];

    WState S;
    S.m31 = (lane == 31) ? 1.f : 0.f;
    const int* trow = tgt + (size_t)n * SS;
#pragma unroll
    for (int j = 0; j < 9; j++) S.a[j] = 0.f;

    // per-lane emission pointers at row 0: blank + this lane's 4 label classes
    const float* base = lp + (size_t)n * CC;
    const float* pB = base;                 // class 0 (blank) — warp-uniform addr
    int c0, c1, c2, c3;
    {
        int k = 4 * lane;
        c0 = trow[k]; c1 = trow[k + 1]; c2 = trow[k + 2]; c3 = trow[k + 3];
        S.sk[0] = (k >= 1 && trow[k - 1] != c0) ? 1.f : 0.f;
        S.sk[1] = (c0 != c1) ? 1.f : 0.f;
        S.sk[2] = (c1 != c2) ? 1.f : 0.f;
        S.sk[3] = (c2 != c3) ? 1.f : 0.f;
    }
    const float* p0 = base + c0;
    const float* p1 = base + c1;
    const float* p2 = base + c2;
    const float* p3 = base + c3;

    // ---- prologue ----
    // t=0 init values (lane 0 only consumes)
    float vB0 = pB[0], v00 = p0[0];
    // raw rows 1..5: row1 -> temp (exp'd now), rows 2..5 -> slots 2,3,0,1 (slot = row & 3)
    float RAW[4][5], r1[5], Pa[5], Pb[5];
    {
        const float* ps[5] = {pB, p0, p1, p2, p3};
#pragma unroll
        for (int j = 0; j < 5; j++) {
            r1[j]        = ps[j][1 * NBC];
            RAW[2][j]    = ps[j][2 * NBC];
            RAW[3][j]    = ps[j][3 * NBC];
            RAW[0][j]    = ps[j][4 * NBC];
            RAW[1][j]    = ps[j][5 * NBC];
        }
    }
    exp5(Pa, r1);                        // p(row 1) for first step
    // advance pointers to block base row tb+5 = 6
    pB += 6 * NBC; p0 += 6 * NBC; p1 += 6 * NBC; p2 += 6 * NBC; p3 += 6 * NBC;

    // alpha at t=0: lattice positions 0 (blank) and 1 (first label), lane 0
    if (lane == 0) {
        S.a[0] = __expf(vB0);
        S.a[1] = __expf(v00);
    }
    S.elane = 0;
    S.empty = (lane != 0);
    S.pAr   = __shfl_up_sync(0xffffffffu, S.a[7], 1);
    S.eprev = __shfl_up_sync(0xffffffffu, S.elane, 1);
    if (lane == 0) { S.pAr = 0.f; S.eprev = S.elane; }

    // ---- main loop: blocks of 4 steps, tb = 1, 5, 9, ... (tb & 3 == 1) ----
    int tb = 1;
    for (; tb + 3 < Tn; tb += 4) {
        bool k0 = tb + 5 < TT, k1 = tb + 6 < TT, k2 = tb + 7 < TT, k3 = tb + 8 < TT;
        // steps t = tb..tb+3; exp slots (t+1)&3 = 2,3,0,1; RESC on 2nd/4th
        bstep<2, 0, false>(S, lane, RAW, Pa, Pb, pB, p0, p1, p2, p3, k0);
        bstep<3, 1, true >(S, lane, RAW, Pb, Pa, pB, p0, p1, p2, p3, k1);
        bstep<0, 2, false>(S, lane, RAW, Pa, Pb, pB, p0, p1, p2, p3, k2);
        bstep<1, 3, true >(S, lane, RAW, Pb, Pa, pB, p0, p1, p2, p3, k3);
        pB += 4 * NBC; p0 += 4 * NBC; p1 += 4 * NBC; p2 += 4 * NBC; p3 += 4 * NBC;
    }

    // ---- tail: 1..3 steps (rows tb+1.. already resident in RAW) ----
    int t = tb;
    if (t < Tn) { exp5(Pb, RAW[2]); ctc_core<true>(S, lane, Pa); t++; }  // p(tb) in Pa
    if (t < Tn) { exp5(Pa, RAW[3]); ctc_core<true>(S, lane, Pb); t++; }
    if (t < Tn) {                    ctc_core<true>(S, lane, Pa); t++; }

    // ---- finalize: combine alpha[2*tl] + alpha[2*tl-1] with per-lane exponents ----
#pragma unroll
    for (int j = 0; j < 8; j++)
        dmp[w][8 * lane + j] = S.a[j];
    if (lane == 31) dmp[w][256] = S.a[8];
    ed[w][lane] = S.elane;
    __syncwarp();
    if (lane == 0) {
        int s1 = 2 * tl, s2 = s1 - 1;
        float va = dmp[w][s1]; int ea = ed[w][min(s1 >> 3, 31)];
        float vb = dmp[w][s2]; int eb = ed[w][s2 >> 3];
        int emax = max(ea, eb);
        float v = va * exp2c(ea - emax) + vb * exp2c(eb - emax);
        float loss = -((__log2f(v) + (float)emax) * 0.69314718055994530942f);
        if (!isfinite(loss) || !(loss < 1e10f)) loss = 0.f;  // zero_infinity
        out[n] = loss;
    }
}

extern "C" void kernel_launch(void* const* d_in, const int* in_sizes, int n_in,
                              void* d_out, int out_size) {
    const float* lp   = (const float*)d_in[0];
    const int*   tgt  = (const int*)d_in[1];
    const int*   ilen = (const int*)d_in[2];
    const int*   tlen = (const int*)d_in[3];
    float*       out  = (float*)d_out;
    int nb = out_size;                 // N
    int blocks = (nb + WPB - 1) / WPB; // 128
    ctc_kernel<<<blocks, WPB * 32>>>(lp, tgt, ilen, tlen, out, nb);
}